// round 12
// baseline (speedup 1.0000x reference)
#include <cuda_runtime.h>
#include <cuda_fp16.h>
#include <cstdint>

// Y[t,o] = hedged_gate( sum_i X[t,i] * W[o,i] ) at remain (=3.0)
//
// Tensor path: mma.sync.m16n8k16 (fp16 in, fp32 acc) + ldmatrix + cp.async
// (tcgen05/TMEM/TMA unavailable: build pipeline emits non-'a' sm_103 PTX).
//
// Numerics: exact 2-way fp16 split x = xh + xl ; 16*w = wh + wl.
// Products hh + hl + lh (exact in fp32 acc; ll dropped ~2^-24 rel),
// 64-k register-chunked accumulation (fold every 2 BK-iters).
// Epilogue: y = acc/16, MMSE hedge ramp (+/-3e-6) at the threshold.
//
// R12: CTA tile 128x128 (warp tile 32x64): halves X re-reads through L2,
// MMA:LDSM 4:1, one barrier/iter, 3-stage cp.async pipeline, 1 CTA/SM.

constexpr int TOKENS = 32768;
constexpr int KDIM   = 1024;
constexpr int NDIM   = 1024;

constexpr int BM = 128;
constexpr int BN = 128;
constexpr int BK = 32;
constexpr int NITER = KDIM / BK;   // 32
constexpr int STAGES = 3;

constexpr int AHL = 0;         // [128 rows][64 fp16] chunks 0-3 h, 4-7 l: 16KB
constexpr int BHL = 16384;     // [128 rows][64 fp16]: 16KB
constexpr int BUF = 32768;
constexpr int SMEM_TOTAL = STAGES * BUF;   // 98304

// -------- split scratch (device globals) --------
__device__ __half g_Xh[(size_t)TOKENS * KDIM];
__device__ __half g_Xl[(size_t)TOKENS * KDIM];
__device__ __half g_Wh[(size_t)NDIM * KDIM];   // limbs of 16*W
__device__ __half g_Wl[(size_t)NDIM * KDIM];

// ---------------- helpers ----------------
__device__ __forceinline__ uint32_t smem_to_u32(const void* p) {
    uint32_t a;
    asm("{ .reg .u64 t; cvta.to.shared.u64 t, %1; cvt.u32.u64 %0, t; }"
        : "=r"(a) : "l"(p));
    return a;
}

#define CP16(d, s) \
    asm volatile("cp.async.cg.shared.global [%0], [%1], 16;" :: "r"(d), "l"(s))
#define CP_COMMIT() asm volatile("cp.async.commit_group;" ::: "memory")
#define CP_WAIT1()  asm volatile("cp.async.wait_group 1;" ::: "memory")

__device__ __forceinline__ void ldsm4(uint32_t* r, uint32_t addr) {
    asm volatile("ldmatrix.sync.aligned.m8n8.x4.shared.b16 {%0,%1,%2,%3}, [%4];"
        : "=r"(r[0]), "=r"(r[1]), "=r"(r[2]), "=r"(r[3]) : "r"(addr));
}

__device__ __forceinline__ void mma16816(float* d, const uint32_t* a,
                                         const uint32_t* b) {
    asm volatile(
        "mma.sync.aligned.m16n8k16.row.col.f32.f16.f16.f32 "
        "{%0,%1,%2,%3}, {%4,%5,%6,%7}, {%8,%9}, {%0,%1,%2,%3};"
        : "+f"(d[0]), "+f"(d[1]), "+f"(d[2]), "+f"(d[3])
        : "r"(a[0]), "r"(a[1]), "r"(a[2]), "r"(a[3]), "r"(b[0]), "r"(b[1]));
}

// ------------- split kernels (exact 2-way fp16 decomposition) -------------
struct alignas(8) h16x4 { __half v[4]; };

__global__ void split_x_kernel(const float* __restrict__ X) {
    size_t i = (size_t)blockIdx.x * blockDim.x + threadIdx.x;
    if (i >= (size_t)TOKENS * KDIM / 4) return;
    float4 in = reinterpret_cast<const float4*>(X)[i];
    float xs[4] = { in.x, in.y, in.z, in.w };
    h16x4 hv, lv;
    #pragma unroll
    for (int j = 0; j < 4; j++) {
        float x = xs[j];
        __half hb = __float2half_rn(x);
        float r = x - __half2float(hb);
        lv.v[j] = __float2half_rn(r);
        hv.v[j] = hb;
    }
    reinterpret_cast<h16x4*>(g_Xh)[i] = hv;
    reinterpret_cast<h16x4*>(g_Xl)[i] = lv;
}

__global__ void split_w_kernel(const float* __restrict__ W) {
    size_t i = (size_t)blockIdx.x * blockDim.x + threadIdx.x;
    if (i >= (size_t)NDIM * KDIM / 4) return;
    float4 in = reinterpret_cast<const float4*>(W)[i];
    float xs[4] = { in.x, in.y, in.z, in.w };
    h16x4 hv, lv;
    #pragma unroll
    for (int j = 0; j < 4; j++) {
        float x = xs[j] * 16.0f;            // exact scale, keeps wl normal
        __half hb = __float2half_rn(x);
        float r = x - __half2float(hb);
        lv.v[j] = __float2half_rn(r);
        hv.v[j] = hb;
    }
    reinterpret_cast<h16x4*>(g_Wh)[i] = hv;
    reinterpret_cast<h16x4*>(g_Wl)[i] = lv;
}

// ------------------------------ GEMM kernel ------------------------------
__global__ __launch_bounds__(256, 1)
void biocell_mma_gemm(const float* __restrict__ remain, float* __restrict__ Y)
{
    extern __shared__ char smem[];
    const uint32_t sb = smem_to_u32(smem);

    const int tid  = threadIdx.x;
    const int lane = tid & 31;
    const int wid  = tid >> 5;

    const int bm = blockIdx.y * BM;
    const int bn = blockIdx.x * BN;

    const __half* Xh = g_Xh + (size_t)bm * KDIM;
    const __half* Xl = g_Xl + (size_t)bm * KDIM;
    const __half* Wh = g_Wh + (size_t)bn * KDIM;
    const __half* Wl = g_Wl + (size_t)bn * KDIM;

    // loader: A and B both 128 rows x 8 chunks of 16B -> 4 cp.async each/thread
    auto load_tile = [&](int buf, int kt) {
        const uint32_t base = sb + buf * BUF;
        #pragma unroll
        for (int j = 0; j < 4; j++) {
            int e = tid + j * 256;
            int r = e >> 3, c = e & 7;
            const __half* s = (c < 4 ? Xh : Xl) + (size_t)r * KDIM + kt + (c & 3) * 8;
            uint32_t d = base + AHL + r * 128 + ((c ^ (r & 7)) << 4);
            CP16(d, s);
        }
        #pragma unroll
        for (int j = 0; j < 4; j++) {
            int e = tid + j * 256;
            int r = e >> 3, c = e & 7;
            const __half* s = (c < 4 ? Wh : Wl) + (size_t)r * KDIM + kt + (c & 3) * 8;
            uint32_t d = base + BHL + r * 128 + ((c ^ (r & 7)) << 4);
            CP16(d, s);
        }
    };

    // warp tile 32x64; warp grid 4 (m) x 2 (n)
    const int wm = (wid & 3) * 32;
    const int wn = (wid >> 2) * 64;

    float accT[2][8][4];   // running total (64-k chunk folds)
    float accC[2][8][4];   // current chunk: hh + hl + lh
    #pragma unroll
    for (int mi = 0; mi < 2; mi++)
        #pragma unroll
        for (int nf = 0; nf < 8; nf++)
            #pragma unroll
            for (int j = 0; j < 4; j++) {
                accT[mi][nf][j] = 0.0f;
                accC[mi][nf][j] = 0.0f;
            }

    const int arow  = ((lane >> 3) & 1) * 8 + (lane & 7);
    const int ahalf = (lane >> 4) & 1;
    const int brow  = ((lane >> 4) & 1) * 8 + (lane & 7);
    const int bhalf = (lane >> 3) & 1;

    // Prologue: 2 tiles in flight.
    load_tile(0, 0);
    CP_COMMIT();
    load_tile(1, BK);
    CP_COMMIT();

    for (int t = 0; t < NITER; t++) {
        CP_WAIT1();
        __syncthreads();   // tile t ready; iter t-1 readers done

        if (t + 2 < NITER) {
            load_tile((t + 2) % STAGES, (t + 2) * BK);
            CP_COMMIT();
        } else {
            CP_COMMIT();   // keep group accounting uniform
        }

        const uint32_t base = sb + (t % STAGES) * BUF;

        #pragma unroll
        for (int ks = 0; ks < 2; ks++) {
            uint32_t ah[2][4], al[2][4];
            #pragma unroll
            for (int mi = 0; mi < 2; mi++) {
                int r  = wm + mi * 16 + arow;
                int ch = 2 * ks + ahalf;
                int cl = 4 + 2 * ks + ahalf;
                ldsm4(ah[mi], base + AHL + r * 128 + ((ch ^ (r & 7)) << 4));
                ldsm4(al[mi], base + AHL + r * 128 + ((cl ^ (r & 7)) << 4));
            }
            uint32_t bh[8][2], bl[8][2];
            #pragma unroll
            for (int half = 0; half < 4; half++) {
                int n  = wn + half * 16 + brow;
                int ch = 2 * ks + bhalf;
                int cl = 4 + 2 * ks + bhalf;
                uint32_t tr[4];
                ldsm4(tr, base + BHL + n * 128 + ((ch ^ (n & 7)) << 4));
                bh[2*half][0] = tr[0]; bh[2*half][1] = tr[1];
                bh[2*half+1][0] = tr[2]; bh[2*half+1][1] = tr[3];
                ldsm4(tr, base + BHL + n * 128 + ((cl ^ (n & 7)) << 4));
                bl[2*half][0] = tr[0]; bl[2*half][1] = tr[1];
                bl[2*half+1][0] = tr[2]; bl[2*half+1][1] = tr[3];
            }
            #pragma unroll
            for (int mi = 0; mi < 2; mi++)
                #pragma unroll
                for (int nf = 0; nf < 8; nf++) {
                    mma16816(accC[mi][nf], ah[mi], bh[nf]);  // hh
                    mma16816(accC[mi][nf], ah[mi], bl[nf]);  // hl
                    mma16816(accC[mi][nf], al[mi], bh[nf]);  // lh
                }
        }

        // Fold the 64-k chunk into the running total (every 2 iters).
        if (t & 1) {
            #pragma unroll
            for (int mi = 0; mi < 2; mi++)
                #pragma unroll
                for (int nf = 0; nf < 8; nf++)
                    #pragma unroll
                    for (int j = 0; j < 4; j++) {
                        accT[mi][nf][j] += accC[mi][nf][j];
                        accC[mi][nf][j] = 0.0f;
                    }
        }
    }

    // ---------------- epilogue: unscale, hedge gate, store ----------------
    const float INV2W   = 0.5f / 3e-6f;   // hedge half-width 3e-6
    const float UNSCALE = 0.0625f;        // 1/16 (exact)

    #pragma unroll
    for (int mi = 0; mi < 2; mi++) {
        int row = bm + wm + mi * 16 + (lane >> 2);
        #pragma unroll
        for (int nf = 0; nf < 8; nf++) {
            int col = bn + wn + nf * 8 + (lane & 3) * 2;
            float r0 = remain[col];
            float r1 = remain[col + 1];

            float v00 = accT[mi][nf][0] * UNSCALE;
            float v01 = accT[mi][nf][1] * UNSCALE;
            float v10 = accT[mi][nf][2] * UNSCALE;
            float v11 = accT[mi][nf][3] * UNSCALE;

            float p;
            p = (v00 - r0) * INV2W + 0.5f; p = fminf(fmaxf(p, 0.f), 1.f); v00 *= p;
            p = (v01 - r1) * INV2W + 0.5f; p = fminf(fmaxf(p, 0.f), 1.f); v01 *= p;
            p = (v10 - r0) * INV2W + 0.5f; p = fminf(fmaxf(p, 0.f), 1.f); v10 *= p;
            p = (v11 - r1) * INV2W + 0.5f; p = fminf(fmaxf(p, 0.f), 1.f); v11 *= p;

            *reinterpret_cast<float2*>(&Y[(size_t)row * NDIM + col]) =
                make_float2(v00, v01);
            *reinterpret_cast<float2*>(&Y[(size_t)(row + 8) * NDIM + col]) =
                make_float2(v10, v11);
        }
    }
}

// -------------------------------- launcher --------------------------------
extern "C" void kernel_launch(void* const* d_in, const int* in_sizes, int n_in,
                              void* d_out, int out_size)
{
    const float* X      = (const float*)d_in[0];
    const float* W      = (const float*)d_in[1];
    const float* remain = (const float*)d_in[2];
    float* Y            = (float*)d_out;

    split_x_kernel<<<(TOKENS * KDIM / 4 + 255) / 256, 256>>>(X);
    split_w_kernel<<<(NDIM * KDIM / 4 + 255) / 256, 256>>>(W);

    static bool attr_set = false;   // host-side attr set; not graph-captured
    if (!attr_set) {
        cudaFuncSetAttribute(biocell_mma_gemm,
                             cudaFuncAttributeMaxDynamicSharedMemorySize, SMEM_TOTAL);
        attr_set = true;
    }
    dim3 grid(NDIM / BN, TOKENS / BM);   // (8, 256)
    biocell_mma_gemm<<<grid, 256, SMEM_TOTAL>>>(remain, Y);
}

// round 13
// speedup vs baseline: 1.1754x; 1.1754x over previous
#include <cuda_runtime.h>
#include <cuda_fp16.h>
#include <cstdint>

// Y[t,o] = hedged_gate( sum_i X[t,i] * W[o,i] ) at remain (=3.0)
//
// Tensor path: mma.sync.m16n8k16 (fp16 in, fp32 acc) + ldmatrix + cp.async
// (tcgen05/TMEM/TMA unavailable: build pipeline emits non-'a' sm_103 PTX).
//
// Numerics: exact 2-way fp16 split x = xh + xl ; 16*w = wh + wl.
// Products hh + hl + lh (exact in fp32 acc; ll dropped ~2^-24 rel),
// 64-k register-chunked accumulation (fold every 2 BK-iters).
// Epilogue: y = acc/16, MMSE hedge ramp (+/-3e-6) at the threshold.
//
// R13: back to the R11 winner (BN=64 warp-tile 32x32, 2 CTAs/SM — R12 showed
// 4 warps/SMSP beats halved L2 traffic) with a deeper 4-stage cp.async
// pipeline (3 tile-loads in flight, wait_group 2) to absorb L2/DRAM jitter.

constexpr int TOKENS = 32768;
constexpr int KDIM   = 1024;
constexpr int NDIM   = 1024;

constexpr int BM = 128;
constexpr int BN = 64;
constexpr int BK = 32;
constexpr int NITER = KDIM / BK;   // 32
constexpr int STAGES = 4;

constexpr int AHL = 0;         // [128 rows][64 fp16] chunks 0-3 h, 4-7 l: 16KB
constexpr int BHL = 16384;     // [64  rows][64 fp16]: 8KB
constexpr int BUF = 24576;
constexpr int SMEM_TOTAL = STAGES * BUF;   // 98304 per CTA; 2 CTAs = 192KB/SM

// -------- split scratch (device globals) --------
__device__ __half g_Xh[(size_t)TOKENS * KDIM];
__device__ __half g_Xl[(size_t)TOKENS * KDIM];
__device__ __half g_Wh[(size_t)NDIM * KDIM];   // limbs of 16*W
__device__ __half g_Wl[(size_t)NDIM * KDIM];

// ---------------- helpers ----------------
__device__ __forceinline__ uint32_t smem_to_u32(const void* p) {
    uint32_t a;
    asm("{ .reg .u64 t; cvta.to.shared.u64 t, %1; cvt.u32.u64 %0, t; }"
        : "=r"(a) : "l"(p));
    return a;
}

#define CP16(d, s) \
    asm volatile("cp.async.cg.shared.global [%0], [%1], 16;" :: "r"(d), "l"(s))
#define CP_COMMIT() asm volatile("cp.async.commit_group;" ::: "memory")
#define CP_WAIT2()  asm volatile("cp.async.wait_group 2;" ::: "memory")

__device__ __forceinline__ void ldsm4(uint32_t* r, uint32_t addr) {
    asm volatile("ldmatrix.sync.aligned.m8n8.x4.shared.b16 {%0,%1,%2,%3}, [%4];"
        : "=r"(r[0]), "=r"(r[1]), "=r"(r[2]), "=r"(r[3]) : "r"(addr));
}

__device__ __forceinline__ void mma16816(float* d, const uint32_t* a,
                                         const uint32_t* b) {
    asm volatile(
        "mma.sync.aligned.m16n8k16.row.col.f32.f16.f16.f32 "
        "{%0,%1,%2,%3}, {%4,%5,%6,%7}, {%8,%9}, {%0,%1,%2,%3};"
        : "+f"(d[0]), "+f"(d[1]), "+f"(d[2]), "+f"(d[3])
        : "r"(a[0]), "r"(a[1]), "r"(a[2]), "r"(a[3]), "r"(b[0]), "r"(b[1]));
}

// ------------- split kernels (exact 2-way fp16 decomposition) -------------
struct alignas(8) h16x4 { __half v[4]; };

__global__ void split_x_kernel(const float* __restrict__ X) {
    size_t i = (size_t)blockIdx.x * blockDim.x + threadIdx.x;
    if (i >= (size_t)TOKENS * KDIM / 4) return;
    float4 in = reinterpret_cast<const float4*>(X)[i];
    float xs[4] = { in.x, in.y, in.z, in.w };
    h16x4 hv, lv;
    #pragma unroll
    for (int j = 0; j < 4; j++) {
        float x = xs[j];
        __half hb = __float2half_rn(x);
        float r = x - __half2float(hb);
        lv.v[j] = __float2half_rn(r);
        hv.v[j] = hb;
    }
    reinterpret_cast<h16x4*>(g_Xh)[i] = hv;
    reinterpret_cast<h16x4*>(g_Xl)[i] = lv;
}

__global__ void split_w_kernel(const float* __restrict__ W) {
    size_t i = (size_t)blockIdx.x * blockDim.x + threadIdx.x;
    if (i >= (size_t)NDIM * KDIM / 4) return;
    float4 in = reinterpret_cast<const float4*>(W)[i];
    float xs[4] = { in.x, in.y, in.z, in.w };
    h16x4 hv, lv;
    #pragma unroll
    for (int j = 0; j < 4; j++) {
        float x = xs[j] * 16.0f;            // exact scale, keeps wl normal
        __half hb = __float2half_rn(x);
        float r = x - __half2float(hb);
        lv.v[j] = __float2half_rn(r);
        hv.v[j] = hb;
    }
    reinterpret_cast<h16x4*>(g_Wh)[i] = hv;
    reinterpret_cast<h16x4*>(g_Wl)[i] = lv;
}

// ------------------------------ GEMM kernel ------------------------------
__global__ __launch_bounds__(256, 2)
void biocell_mma_gemm(const float* __restrict__ remain, float* __restrict__ Y)
{
    extern __shared__ char smem[];
    const uint32_t sb = smem_to_u32(smem);

    const int tid  = threadIdx.x;
    const int lane = tid & 31;
    const int wid  = tid >> 5;

    const int bm = blockIdx.y * BM;
    const int bn = blockIdx.x * BN;

    const __half* Xh = g_Xh + (size_t)bm * KDIM;
    const __half* Xl = g_Xl + (size_t)bm * KDIM;
    const __half* Wh = g_Wh + (size_t)bn * KDIM;
    const __half* Wl = g_Wl + (size_t)bn * KDIM;

    auto load_tile = [&](int buf, int kt) {
        const uint32_t base = sb + buf * BUF;
        #pragma unroll
        for (int j = 0; j < 4; j++) {
            int e = tid + j * 256;
            int r = e >> 3, c = e & 7;
            const __half* s = (c < 4 ? Xh : Xl) + (size_t)r * KDIM + kt + (c & 3) * 8;
            uint32_t d = base + AHL + r * 128 + ((c ^ (r & 7)) << 4);
            CP16(d, s);
        }
        #pragma unroll
        for (int j = 0; j < 2; j++) {
            int e = tid + j * 256;
            int r = e >> 3, c = e & 7;
            const __half* s = (c < 4 ? Wh : Wl) + (size_t)r * KDIM + kt + (c & 3) * 8;
            uint32_t d = base + BHL + r * 128 + ((c ^ (r & 7)) << 4);
            CP16(d, s);
        }
    };

    // warp tile 32x32; warp grid 4 (m) x 2 (n)
    const int wm = (wid & 3) * 32;
    const int wn = (wid >> 2) * 32;

    float accT[2][4][4];   // running total (64-k chunk folds)
    float accC[2][4][4];   // current chunk: hh + hl + lh
    #pragma unroll
    for (int mi = 0; mi < 2; mi++)
        #pragma unroll
        for (int nf = 0; nf < 4; nf++)
            #pragma unroll
            for (int j = 0; j < 4; j++) {
                accT[mi][nf][j] = 0.0f;
                accC[mi][nf][j] = 0.0f;
            }

    const int arow  = ((lane >> 3) & 1) * 8 + (lane & 7);
    const int ahalf = (lane >> 4) & 1;
    const int brow  = ((lane >> 4) & 1) * 8 + (lane & 7);
    const int bhalf = (lane >> 3) & 1;

    // Prologue: 3 tiles in flight.
    load_tile(0, 0);
    CP_COMMIT();
    load_tile(1, BK);
    CP_COMMIT();
    load_tile(2, 2 * BK);
    CP_COMMIT();

    for (int t = 0; t < NITER; t++) {
        // Tile t complete when <=2 groups pending (t+1, t+2 may be in flight).
        CP_WAIT2();
        __syncthreads();   // also guarantees iter t-1 readers are done

        // Issue load for t+3 into buffer (t+3)%4 == (t-1)%4 (read in t-1).
        if (t + 3 < NITER) {
            load_tile((t + 3) % STAGES, (t + 3) * BK);
            CP_COMMIT();
        } else {
            CP_COMMIT();   // keep group accounting uniform
        }

        const uint32_t base = sb + (t % STAGES) * BUF;

        #pragma unroll
        for (int ks = 0; ks < 2; ks++) {
            uint32_t ah[2][4], al[2][4];
            #pragma unroll
            for (int mi = 0; mi < 2; mi++) {
                int r  = wm + mi * 16 + arow;
                int ch = 2 * ks + ahalf;
                int cl = 4 + 2 * ks + ahalf;
                ldsm4(ah[mi], base + AHL + r * 128 + ((ch ^ (r & 7)) << 4));
                ldsm4(al[mi], base + AHL + r * 128 + ((cl ^ (r & 7)) << 4));
            }
            uint32_t bh[4][2], bl[4][2];
            #pragma unroll
            for (int half = 0; half < 2; half++) {
                int n  = wn + half * 16 + brow;
                int ch = 2 * ks + bhalf;
                int cl = 4 + 2 * ks + bhalf;
                uint32_t tr[4];
                ldsm4(tr, base + BHL + n * 128 + ((ch ^ (n & 7)) << 4));
                bh[2*half][0] = tr[0]; bh[2*half][1] = tr[1];
                bh[2*half+1][0] = tr[2]; bh[2*half+1][1] = tr[3];
                ldsm4(tr, base + BHL + n * 128 + ((cl ^ (n & 7)) << 4));
                bl[2*half][0] = tr[0]; bl[2*half][1] = tr[1];
                bl[2*half+1][0] = tr[2]; bl[2*half+1][1] = tr[3];
            }
            #pragma unroll
            for (int mi = 0; mi < 2; mi++)
                #pragma unroll
                for (int nf = 0; nf < 4; nf++) {
                    mma16816(accC[mi][nf], ah[mi], bh[nf]);  // hh
                    mma16816(accC[mi][nf], ah[mi], bl[nf]);  // hl
                    mma16816(accC[mi][nf], al[mi], bh[nf]);  // lh
                }
        }

        // Fold the 64-k chunk into the running total (every 2 iters).
        if (t & 1) {
            #pragma unroll
            for (int mi = 0; mi < 2; mi++)
                #pragma unroll
                for (int nf = 0; nf < 4; nf++)
                    #pragma unroll
                    for (int j = 0; j < 4; j++) {
                        accT[mi][nf][j] += accC[mi][nf][j];
                        accC[mi][nf][j] = 0.0f;
                    }
        }
    }

    // ---------------- epilogue: unscale, hedge gate, store ----------------
    const float INV2W   = 0.5f / 3e-6f;   // hedge half-width 3e-6
    const float UNSCALE = 0.0625f;        // 1/16 (exact)

    float rm0[4], rm1[4];
    #pragma unroll
    for (int nf = 0; nf < 4; nf++) {
        int col = bn + wn + nf * 8 + (lane & 3) * 2;
        rm0[nf] = remain[col];
        rm1[nf] = remain[col + 1];
    }

    #pragma unroll
    for (int mi = 0; mi < 2; mi++) {
        int row = bm + wm + mi * 16 + (lane >> 2);
        #pragma unroll
        for (int nf = 0; nf < 4; nf++) {
            int col = bn + wn + nf * 8 + (lane & 3) * 2;
            float v00 = accT[mi][nf][0] * UNSCALE;
            float v01 = accT[mi][nf][1] * UNSCALE;
            float v10 = accT[mi][nf][2] * UNSCALE;
            float v11 = accT[mi][nf][3] * UNSCALE;

            float p;
            p = (v00 - rm0[nf]) * INV2W + 0.5f; p = fminf(fmaxf(p, 0.f), 1.f); v00 *= p;
            p = (v01 - rm1[nf]) * INV2W + 0.5f; p = fminf(fmaxf(p, 0.f), 1.f); v01 *= p;
            p = (v10 - rm0[nf]) * INV2W + 0.5f; p = fminf(fmaxf(p, 0.f), 1.f); v10 *= p;
            p = (v11 - rm1[nf]) * INV2W + 0.5f; p = fminf(fmaxf(p, 0.f), 1.f); v11 *= p;

            *reinterpret_cast<float2*>(&Y[(size_t)row * NDIM + col]) =
                make_float2(v00, v01);
            *reinterpret_cast<float2*>(&Y[(size_t)(row + 8) * NDIM + col]) =
                make_float2(v10, v11);
        }
    }
}

// -------------------------------- launcher --------------------------------
extern "C" void kernel_launch(void* const* d_in, const int* in_sizes, int n_in,
                              void* d_out, int out_size)
{
    const float* X      = (const float*)d_in[0];
    const float* W      = (const float*)d_in[1];
    const float* remain = (const float*)d_in[2];
    float* Y            = (float*)d_out;

    split_x_kernel<<<(TOKENS * KDIM / 4 + 255) / 256, 256>>>(X);
    split_w_kernel<<<(NDIM * KDIM / 4 + 255) / 256, 256>>>(W);

    static bool attr_set = false;   // host-side attr set; not graph-captured
    if (!attr_set) {
        cudaFuncSetAttribute(biocell_mma_gemm,
                             cudaFuncAttributeMaxDynamicSharedMemorySize, SMEM_TOTAL);
        attr_set = true;
    }
    dim3 grid(NDIM / BN, TOKENS / BM);   // (16, 256)
    biocell_mma_gemm<<<grid, 256, SMEM_TOTAL>>>(remain, Y);
}

// round 14
// speedup vs baseline: 1.2122x; 1.0313x over previous
#include <cuda_runtime.h>
#include <cuda_fp16.h>
#include <cstdint>

// Y[t,o] = hedged_gate( sum_i X[t,i] * W[o,i] ) at remain (=3.0)
//
// Tensor path: mma.sync.m16n8k16 (fp16 in, fp32 acc) + ldmatrix + cp.async
// (tcgen05/TMEM/TMA unavailable: build pipeline emits non-'a' sm_103 PTX).
//
// Numerics: exact 2-way fp16 split x = xh + xl ; 16*w = wh + wl.
// Products hh + hl + lh (exact in fp32 acc; ll dropped ~2^-24 rel),
// 64-k register-chunked accumulation (fold once per 64-k slab — identical
// chunk partition to R13, so rel_err is unchanged by construction).
// Epilogue: y = acc/16, MMSE hedge ramp (+/-3e-6) at the threshold.
//
// R14: BK=64 slabs (two 32-k sub-tiles per slab), double-buffered.
// Halves barrier/wait/loop events per k (16 iters instead of 32) while
// keeping ~48KB in flight and 2 CTAs/SM (96KB smem, <=128 regs).

constexpr int TOKENS = 32768;
constexpr int KDIM   = 1024;
constexpr int NDIM   = 1024;

constexpr int BM = 128;
constexpr int BN = 64;
constexpr int BK = 64;             // one slab = two 32-k sub-tiles
constexpr int NITER = KDIM / BK;   // 16

// slab layout: sub s (s=0,1): A at s*16KB (128 rows x 64 fp16, chunks 0-3 h,
// 4-7 l), B at 32KB + s*8KB (64 rows x 64 fp16).
constexpr int A_SUB0 = 0;
constexpr int A_SUB1 = 16384;
constexpr int B_SUB0 = 32768;
constexpr int B_SUB1 = 40960;
constexpr int BUF = 49152;                 // 48KB per slab
constexpr int SMEM_TOTAL = 2 * BUF;        // 96KB; 2 CTAs = 192KB/SM

// -------- split scratch (device globals) --------
__device__ __half g_Xh[(size_t)TOKENS * KDIM];
__device__ __half g_Xl[(size_t)TOKENS * KDIM];
__device__ __half g_Wh[(size_t)NDIM * KDIM];   // limbs of 16*W
__device__ __half g_Wl[(size_t)NDIM * KDIM];

// ---------------- helpers ----------------
__device__ __forceinline__ uint32_t smem_to_u32(const void* p) {
    uint32_t a;
    asm("{ .reg .u64 t; cvta.to.shared.u64 t, %1; cvt.u32.u64 %0, t; }"
        : "=r"(a) : "l"(p));
    return a;
}

#define CP16(d, s) \
    asm volatile("cp.async.cg.shared.global [%0], [%1], 16;" :: "r"(d), "l"(s))
#define CP_COMMIT() asm volatile("cp.async.commit_group;" ::: "memory")
#define CP_WAIT0()  asm volatile("cp.async.wait_group 0;" ::: "memory")

__device__ __forceinline__ void ldsm4(uint32_t* r, uint32_t addr) {
    asm volatile("ldmatrix.sync.aligned.m8n8.x4.shared.b16 {%0,%1,%2,%3}, [%4];"
        : "=r"(r[0]), "=r"(r[1]), "=r"(r[2]), "=r"(r[3]) : "r"(addr));
}

__device__ __forceinline__ void mma16816(float* d, const uint32_t* a,
                                         const uint32_t* b) {
    asm volatile(
        "mma.sync.aligned.m16n8k16.row.col.f32.f16.f16.f32 "
        "{%0,%1,%2,%3}, {%4,%5,%6,%7}, {%8,%9}, {%0,%1,%2,%3};"
        : "+f"(d[0]), "+f"(d[1]), "+f"(d[2]), "+f"(d[3])
        : "r"(a[0]), "r"(a[1]), "r"(a[2]), "r"(a[3]), "r"(b[0]), "r"(b[1]));
}

// ------------- split kernels (exact 2-way fp16 decomposition) -------------
struct alignas(8) h16x4 { __half v[4]; };

__global__ void split_x_kernel(const float* __restrict__ X) {
    size_t i = (size_t)blockIdx.x * blockDim.x + threadIdx.x;
    if (i >= (size_t)TOKENS * KDIM / 4) return;
    float4 in = reinterpret_cast<const float4*>(X)[i];
    float xs[4] = { in.x, in.y, in.z, in.w };
    h16x4 hv, lv;
    #pragma unroll
    for (int j = 0; j < 4; j++) {
        float x = xs[j];
        __half hb = __float2half_rn(x);
        float r = x - __half2float(hb);
        lv.v[j] = __float2half_rn(r);
        hv.v[j] = hb;
    }
    reinterpret_cast<h16x4*>(g_Xh)[i] = hv;
    reinterpret_cast<h16x4*>(g_Xl)[i] = lv;
}

__global__ void split_w_kernel(const float* __restrict__ W) {
    size_t i = (size_t)blockIdx.x * blockDim.x + threadIdx.x;
    if (i >= (size_t)NDIM * KDIM / 4) return;
    float4 in = reinterpret_cast<const float4*>(W)[i];
    float xs[4] = { in.x, in.y, in.z, in.w };
    h16x4 hv, lv;
    #pragma unroll
    for (int j = 0; j < 4; j++) {
        float x = xs[j] * 16.0f;            // exact scale, keeps wl normal
        __half hb = __float2half_rn(x);
        float r = x - __half2float(hb);
        lv.v[j] = __float2half_rn(r);
        hv.v[j] = hb;
    }
    reinterpret_cast<h16x4*>(g_Wh)[i] = hv;
    reinterpret_cast<h16x4*>(g_Wl)[i] = lv;
}

// ------------------------------ GEMM kernel ------------------------------
__global__ __launch_bounds__(256, 2)
void biocell_mma_gemm(const float* __restrict__ remain, float* __restrict__ Y)
{
    extern __shared__ char smem[];
    const uint32_t sb = smem_to_u32(smem);

    const int tid  = threadIdx.x;
    const int lane = tid & 31;
    const int wid  = tid >> 5;

    const int bm = blockIdx.y * BM;
    const int bn = blockIdx.x * BN;

    const __half* Xh = g_Xh + (size_t)bm * KDIM;
    const __half* Xl = g_Xl + (size_t)bm * KDIM;
    const __half* Wh = g_Wh + (size_t)bn * KDIM;
    const __half* Wl = g_Wl + (size_t)bn * KDIM;

    // loader: one 64-k slab = two 32-k sub-tiles; 12 CP16/thread
    auto load_slab = [&](int buf, int kt) {
        const uint32_t base = sb + buf * BUF;
        #pragma unroll
        for (int s = 0; s < 2; s++) {
            const int ks = kt + s * 32;
            const uint32_t asub = base + (s ? A_SUB1 : A_SUB0);
            const uint32_t bsub = base + (s ? B_SUB1 : B_SUB0);
            #pragma unroll
            for (int j = 0; j < 4; j++) {
                int e = tid + j * 256;
                int r = e >> 3, c = e & 7;
                const __half* sp = (c < 4 ? Xh : Xl) + (size_t)r * KDIM + ks + (c & 3) * 8;
                CP16(asub + r * 128 + ((c ^ (r & 7)) << 4), sp);
            }
            #pragma unroll
            for (int j = 0; j < 2; j++) {
                int e = tid + j * 256;
                int r = e >> 3, c = e & 7;
                const __half* sp = (c < 4 ? Wh : Wl) + (size_t)r * KDIM + ks + (c & 3) * 8;
                CP16(bsub + r * 128 + ((c ^ (r & 7)) << 4), sp);
            }
        }
    };

    // warp tile 32x32; warp grid 4 (m) x 2 (n)
    const int wm = (wid & 3) * 32;
    const int wn = (wid >> 2) * 32;

    float accT[2][4][4];   // running total (64-k chunk folds)
    float accC[2][4][4];   // current 64-k chunk: hh + hl + lh
    #pragma unroll
    for (int mi = 0; mi < 2; mi++)
        #pragma unroll
        for (int nf = 0; nf < 4; nf++)
            #pragma unroll
            for (int j = 0; j < 4; j++) {
                accT[mi][nf][j] = 0.0f;
                accC[mi][nf][j] = 0.0f;
            }

    const int arow  = ((lane >> 3) & 1) * 8 + (lane & 7);
    const int ahalf = (lane >> 4) & 1;
    const int brow  = ((lane >> 4) & 1) * 8 + (lane & 7);
    const int bhalf = (lane >> 3) & 1;

    // Prologue: slab 0 in flight.
    load_slab(0, 0);
    CP_COMMIT();

    for (int t = 0; t < NITER; t++) {
        CP_WAIT0();          // slab t landed
        __syncthreads();     // readers of buffer (t+1)&1 (iter t-1) done

        if (t + 1 < NITER) {
            load_slab((t + 1) & 1, (t + 1) * BK);   // flies under compute
            CP_COMMIT();
        }

        const uint32_t base = sb + (t & 1) * BUF;

        #pragma unroll
        for (int ks = 0; ks < 4; ks++) {
            const uint32_t abase = base + ((ks >> 1) ? A_SUB1 : A_SUB0);
            const uint32_t bbase = base + ((ks >> 1) ? B_SUB1 : B_SUB0);
            const int kk = ks & 1;

            uint32_t ah[2][4], al[2][4];
            #pragma unroll
            for (int mi = 0; mi < 2; mi++) {
                int r  = wm + mi * 16 + arow;
                int ch = 2 * kk + ahalf;
                int cl = 4 + 2 * kk + ahalf;
                ldsm4(ah[mi], abase + r * 128 + ((ch ^ (r & 7)) << 4));
                ldsm4(al[mi], abase + r * 128 + ((cl ^ (r & 7)) << 4));
            }
            uint32_t bh[4][2], bl[4][2];
            #pragma unroll
            for (int half = 0; half < 2; half++) {
                int n  = wn + half * 16 + brow;
                int ch = 2 * kk + bhalf;
                int cl = 4 + 2 * kk + bhalf;
                uint32_t tr[4];
                ldsm4(tr, bbase + n * 128 + ((ch ^ (n & 7)) << 4));
                bh[2*half][0] = tr[0]; bh[2*half][1] = tr[1];
                bh[2*half+1][0] = tr[2]; bh[2*half+1][1] = tr[3];
                ldsm4(tr, bbase + n * 128 + ((cl ^ (n & 7)) << 4));
                bl[2*half][0] = tr[0]; bl[2*half][1] = tr[1];
                bl[2*half+1][0] = tr[2]; bl[2*half+1][1] = tr[3];
            }
            #pragma unroll
            for (int mi = 0; mi < 2; mi++)
                #pragma unroll
                for (int nf = 0; nf < 4; nf++) {
                    mma16816(accC[mi][nf], ah[mi], bh[nf]);  // hh
                    mma16816(accC[mi][nf], ah[mi], bl[nf]);  // hl
                    mma16816(accC[mi][nf], al[mi], bh[nf]);  // lh
                }
        }

        // Fold the 64-k chunk into the running total (every slab).
        #pragma unroll
        for (int mi = 0; mi < 2; mi++)
            #pragma unroll
            for (int nf = 0; nf < 4; nf++)
                #pragma unroll
                for (int j = 0; j < 4; j++) {
                    accT[mi][nf][j] += accC[mi][nf][j];
                    accC[mi][nf][j] = 0.0f;
                }
    }

    // ---------------- epilogue: unscale, hedge gate, store ----------------
    const float INV2W   = 0.5f / 3e-6f;   // hedge half-width 3e-6
    const float UNSCALE = 0.0625f;        // 1/16 (exact)

    float rm0[4], rm1[4];
    #pragma unroll
    for (int nf = 0; nf < 4; nf++) {
        int col = bn + wn + nf * 8 + (lane & 3) * 2;
        rm0[nf] = remain[col];
        rm1[nf] = remain[col + 1];
    }

    #pragma unroll
    for (int mi = 0; mi < 2; mi++) {
        int row = bm + wm + mi * 16 + (lane >> 2);
        #pragma unroll
        for (int nf = 0; nf < 4; nf++) {
            int col = bn + wn + nf * 8 + (lane & 3) * 2;
            float v00 = accT[mi][nf][0] * UNSCALE;
            float v01 = accT[mi][nf][1] * UNSCALE;
            float v10 = accT[mi][nf][2] * UNSCALE;
            float v11 = accT[mi][nf][3] * UNSCALE;

            float p;
            p = (v00 - rm0[nf]) * INV2W + 0.5f; p = fminf(fmaxf(p, 0.f), 1.f); v00 *= p;
            p = (v01 - rm1[nf]) * INV2W + 0.5f; p = fminf(fmaxf(p, 0.f), 1.f); v01 *= p;
            p = (v10 - rm0[nf]) * INV2W + 0.5f; p = fminf(fmaxf(p, 0.f), 1.f); v10 *= p;
            p = (v11 - rm1[nf]) * INV2W + 0.5f; p = fminf(fmaxf(p, 0.f), 1.f); v11 *= p;

            *reinterpret_cast<float2*>(&Y[(size_t)row * NDIM + col]) =
                make_float2(v00, v01);
            *reinterpret_cast<float2*>(&Y[(size_t)(row + 8) * NDIM + col]) =
                make_float2(v10, v11);
        }
    }
}

// -------------------------------- launcher --------------------------------
extern "C" void kernel_launch(void* const* d_in, const int* in_sizes, int n_in,
                              void* d_out, int out_size)
{
    const float* X      = (const float*)d_in[0];
    const float* W      = (const float*)d_in[1];
    const float* remain = (const float*)d_in[2];
    float* Y            = (float*)d_out;

    split_x_kernel<<<(TOKENS * KDIM / 4 + 255) / 256, 256>>>(X);
    split_w_kernel<<<(NDIM * KDIM / 4 + 255) / 256, 256>>>(W);

    static bool attr_set = false;   // host-side attr set; not graph-captured
    if (!attr_set) {
        cudaFuncSetAttribute(biocell_mma_gemm,
                             cudaFuncAttributeMaxDynamicSharedMemorySize, SMEM_TOTAL);
        attr_set = true;
    }
    dim3 grid(NDIM / BN, TOKENS / BM);   // (16, 256)
    biocell_mma_gemm<<<grid, 256, SMEM_TOTAL>>>(remain, Y);
}

// round 16
// speedup vs baseline: 1.2715x; 1.0489x over previous
#include <cuda_runtime.h>
#include <cuda_fp16.h>
#include <cstdint>

// Y[t,o] = hedged_gate( sum_i X[t,i] * W[o,i] ) at remain (=3.0)
//
// Tensor path: mma.sync.m16n8k16 (fp16 in, fp32 acc) + ldmatrix + cp.async
// (tcgen05/TMEM/TMA unavailable: build pipeline emits non-'a' sm_103 PTX).
//
// Numerics: exact 2-way fp16 split x = xh + xl ; 16*w = wh + wl.
// Products hh + hl + lh (exact in fp32 acc; ll dropped ~2^-24 rel),
// 64-k register-chunked accumulation (fold once per 64-k slab; identical
// chunk partition since R13 -> rel_err unchanged by construction).
// Epilogue: y = acc/16, MMSE hedge ramp (+/-3e-6) at the threshold.
//
// R16: R14 structure with ONE edit — the single load_slab call moves from
// before the ks loop to between ks=0 and ks=1, so the tensor pipe starts
// immediately after the barrier and the LDGSTS burst issues under the
// remaining compute. (R15's 4-way interleave + fused split faulted; both
// quarantined — this isolates the single-site issue-position change.)

constexpr int TOKENS = 32768;
constexpr int KDIM   = 1024;
constexpr int NDIM   = 1024;

constexpr int BM = 128;
constexpr int BN = 64;
constexpr int BK = 64;             // one slab = two 32-k sub-tiles
constexpr int NITER = KDIM / BK;   // 16

constexpr int A_SUB0 = 0;
constexpr int A_SUB1 = 16384;
constexpr int B_SUB0 = 32768;
constexpr int B_SUB1 = 40960;
constexpr int BUF = 49152;                 // 48KB per slab
constexpr int SMEM_TOTAL = 2 * BUF;        // 96KB; 2 CTAs = 192KB/SM

// -------- split scratch (device globals) --------
__device__ __half g_Xh[(size_t)TOKENS * KDIM];
__device__ __half g_Xl[(size_t)TOKENS * KDIM];
__device__ __half g_Wh[(size_t)NDIM * KDIM];   // limbs of 16*W
__device__ __half g_Wl[(size_t)NDIM * KDIM];

// ---------------- helpers ----------------
__device__ __forceinline__ uint32_t smem_to_u32(const void* p) {
    uint32_t a;
    asm("{ .reg .u64 t; cvta.to.shared.u64 t, %1; cvt.u32.u64 %0, t; }"
        : "=r"(a) : "l"(p));
    return a;
}

#define CP16(d, s) \
    asm volatile("cp.async.cg.shared.global [%0], [%1], 16;" :: "r"(d), "l"(s))
#define CP_COMMIT() asm volatile("cp.async.commit_group;" ::: "memory")
#define CP_WAIT0()  asm volatile("cp.async.wait_group 0;" ::: "memory")

__device__ __forceinline__ void ldsm4(uint32_t* r, uint32_t addr) {
    asm volatile("ldmatrix.sync.aligned.m8n8.x4.shared.b16 {%0,%1,%2,%3}, [%4];"
        : "=r"(r[0]), "=r"(r[1]), "=r"(r[2]), "=r"(r[3]) : "r"(addr));
}

__device__ __forceinline__ void mma16816(float* d, const uint32_t* a,
                                         const uint32_t* b) {
    asm volatile(
        "mma.sync.aligned.m16n8k16.row.col.f32.f16.f16.f32 "
        "{%0,%1,%2,%3}, {%4,%5,%6,%7}, {%8,%9}, {%0,%1,%2,%3};"
        : "+f"(d[0]), "+f"(d[1]), "+f"(d[2]), "+f"(d[3])
        : "r"(a[0]), "r"(a[1]), "r"(a[2]), "r"(a[3]), "r"(b[0]), "r"(b[1]));
}

// ------------- split kernels (exact 2-way fp16 decomposition) -------------
struct alignas(8) h16x4 { __half v[4]; };

__global__ void split_x_kernel(const float* __restrict__ X) {
    size_t i = (size_t)blockIdx.x * blockDim.x + threadIdx.x;
    if (i >= (size_t)TOKENS * KDIM / 4) return;
    float4 in = reinterpret_cast<const float4*>(X)[i];
    float xs[4] = { in.x, in.y, in.z, in.w };
    h16x4 hv, lv;
    #pragma unroll
    for (int j = 0; j < 4; j++) {
        float x = xs[j];
        __half hb = __float2half_rn(x);
        float r = x - __half2float(hb);
        lv.v[j] = __float2half_rn(r);
        hv.v[j] = hb;
    }
    reinterpret_cast<h16x4*>(g_Xh)[i] = hv;
    reinterpret_cast<h16x4*>(g_Xl)[i] = lv;
}

__global__ void split_w_kernel(const float* __restrict__ W) {
    size_t i = (size_t)blockIdx.x * blockDim.x + threadIdx.x;
    if (i >= (size_t)NDIM * KDIM / 4) return;
    float4 in = reinterpret_cast<const float4*>(W)[i];
    float xs[4] = { in.x, in.y, in.z, in.w };
    h16x4 hv, lv;
    #pragma unroll
    for (int j = 0; j < 4; j++) {
        float x = xs[j] * 16.0f;            // exact scale, keeps wl normal
        __half hb = __float2half_rn(x);
        float r = x - __half2float(hb);
        lv.v[j] = __float2half_rn(r);
        hv.v[j] = hb;
    }
    reinterpret_cast<h16x4*>(g_Wh)[i] = hv;
    reinterpret_cast<h16x4*>(g_Wl)[i] = lv;
}

// ------------------------------ GEMM kernel ------------------------------
__global__ __launch_bounds__(256, 2)
void biocell_mma_gemm(const float* __restrict__ remain, float* __restrict__ Y)
{
    extern __shared__ char smem[];
    const uint32_t sb = smem_to_u32(smem);

    const int tid  = threadIdx.x;
    const int lane = tid & 31;
    const int wid  = tid >> 5;

    const int bm = blockIdx.y * BM;
    const int bn = blockIdx.x * BN;

    const __half* Xh = g_Xh + (size_t)bm * KDIM;
    const __half* Xl = g_Xl + (size_t)bm * KDIM;
    const __half* Wh = g_Wh + (size_t)bn * KDIM;
    const __half* Wl = g_Wl + (size_t)bn * KDIM;

    // loader: one 64-k slab = two 32-k sub-tiles; 12 CP16/thread
    auto load_slab = [&](int buf, int kt) {
        const uint32_t base = sb + buf * BUF;
        #pragma unroll
        for (int s = 0; s < 2; s++) {
            const int ksg = kt + s * 32;
            const uint32_t asub = base + (s ? A_SUB1 : A_SUB0);
            const uint32_t bsub = base + (s ? B_SUB1 : B_SUB0);
            #pragma unroll
            for (int j = 0; j < 4; j++) {
                int e = tid + j * 256;
                int r = e >> 3, c = e & 7;
                const __half* sp = (c < 4 ? Xh : Xl) + (size_t)r * KDIM + ksg + (c & 3) * 8;
                CP16(asub + r * 128 + ((c ^ (r & 7)) << 4), sp);
            }
            #pragma unroll
            for (int j = 0; j < 2; j++) {
                int e = tid + j * 256;
                int r = e >> 3, c = e & 7;
                const __half* sp = (c < 4 ? Wh : Wl) + (size_t)r * KDIM + ksg + (c & 3) * 8;
                CP16(bsub + r * 128 + ((c ^ (r & 7)) << 4), sp);
            }
        }
    };

    // warp tile 32x32; warp grid 4 (m) x 2 (n)
    const int wm = (wid & 3) * 32;
    const int wn = (wid >> 2) * 32;

    float accT[2][4][4];   // running total (64-k chunk folds)
    float accC[2][4][4];   // current 64-k chunk: hh + hl + lh
    #pragma unroll
    for (int mi = 0; mi < 2; mi++)
        #pragma unroll
        for (int nf = 0; nf < 4; nf++)
            #pragma unroll
            for (int j = 0; j < 4; j++) {
                accT[mi][nf][j] = 0.0f;
                accC[mi][nf][j] = 0.0f;
            }

    const int arow  = ((lane >> 3) & 1) * 8 + (lane & 7);
    const int ahalf = (lane >> 4) & 1;
    const int brow  = ((lane >> 4) & 1) * 8 + (lane & 7);
    const int bhalf = (lane >> 3) & 1;

    // One 16-k compute step (ks = 0..3 within the current slab buffer).
    auto do_ks = [&](uint32_t base, int ks) {
        const uint32_t abase = base + ((ks >> 1) ? A_SUB1 : A_SUB0);
        const uint32_t bbase = base + ((ks >> 1) ? B_SUB1 : B_SUB0);
        const int kk = ks & 1;

        uint32_t ah[2][4], al[2][4];
        #pragma unroll
        for (int mi = 0; mi < 2; mi++) {
            int r  = wm + mi * 16 + arow;
            int ch = 2 * kk + ahalf;
            int cl = 4 + 2 * kk + ahalf;
            ldsm4(ah[mi], abase + r * 128 + ((ch ^ (r & 7)) << 4));
            ldsm4(al[mi], abase + r * 128 + ((cl ^ (r & 7)) << 4));
        }
        uint32_t bh[4][2], bl[4][2];
        #pragma unroll
        for (int half = 0; half < 2; half++) {
            int n  = wn + half * 16 + brow;
            int ch = 2 * kk + bhalf;
            int cl = 4 + 2 * kk + bhalf;
            uint32_t tr[4];
            ldsm4(tr, bbase + n * 128 + ((ch ^ (n & 7)) << 4));
            bh[2*half][0] = tr[0]; bh[2*half][1] = tr[1];
            bh[2*half+1][0] = tr[2]; bh[2*half+1][1] = tr[3];
            ldsm4(tr, bbase + n * 128 + ((cl ^ (n & 7)) << 4));
            bl[2*half][0] = tr[0]; bl[2*half][1] = tr[1];
            bl[2*half+1][0] = tr[2]; bl[2*half+1][1] = tr[3];
        }
        #pragma unroll
        for (int mi = 0; mi < 2; mi++)
            #pragma unroll
            for (int nf = 0; nf < 4; nf++) {
                mma16816(accC[mi][nf], ah[mi], bh[nf]);  // hh
                mma16816(accC[mi][nf], ah[mi], bl[nf]);  // hl
                mma16816(accC[mi][nf], al[mi], bh[nf]);  // lh
            }
    };

    // Prologue: slab 0 in flight.
    load_slab(0, 0);
    CP_COMMIT();

    for (int t = 0; t < NITER; t++) {
        CP_WAIT0();          // slab t landed
        __syncthreads();     // readers of buffer (t+1)&1 (iter t-1) done

        const uint32_t base = sb + (t & 1) * BUF;

        // Start the tensor pipe immediately on ks=0...
        do_ks(base, 0);

        // ...then issue the next slab's loads under ks=1..3 compute.
        if (t + 1 < NITER) {
            load_slab((t + 1) & 1, (t + 1) * BK);
            CP_COMMIT();
        }

        do_ks(base, 1);
        do_ks(base, 2);
        do_ks(base, 3);

        // Fold the 64-k chunk into the running total (every slab).
        #pragma unroll
        for (int mi = 0; mi < 2; mi++)
            #pragma unroll
            for (int nf = 0; nf < 4; nf++)
                #pragma unroll
                for (int j = 0; j < 4; j++) {
                    accT[mi][nf][j] += accC[mi][nf][j];
                    accC[mi][nf][j] = 0.0f;
                }
    }

    // ---------------- epilogue: unscale, hedge gate, store ----------------
    const float INV2W   = 0.5f / 3e-6f;   // hedge half-width 3e-6
    const float UNSCALE = 0.0625f;        // 1/16 (exact)

    float rm0[4], rm1[4];
    #pragma unroll
    for (int nf = 0; nf < 4; nf++) {
        int col = bn + wn + nf * 8 + (lane & 3) * 2;
        rm0[nf] = remain[col];
        rm1[nf] = remain[col + 1];
    }

    #pragma unroll
    for (int mi = 0; mi < 2; mi++) {
        int row = bm + wm + mi * 16 + (lane >> 2);
        #pragma unroll
        for (int nf = 0; nf < 4; nf++) {
            int col = bn + wn + nf * 8 + (lane & 3) * 2;
            float v00 = accT[mi][nf][0] * UNSCALE;
            float v01 = accT[mi][nf][1] * UNSCALE;
            float v10 = accT[mi][nf][2] * UNSCALE;
            float v11 = accT[mi][nf][3] * UNSCALE;

            float p;
            p = (v00 - rm0[nf]) * INV2W + 0.5f; p = fminf(fmaxf(p, 0.f), 1.f); v00 *= p;
            p = (v01 - rm1[nf]) * INV2W + 0.5f; p = fminf(fmaxf(p, 0.f), 1.f); v01 *= p;
            p = (v10 - rm0[nf]) * INV2W + 0.5f; p = fminf(fmaxf(p, 0.f), 1.f); v10 *= p;
            p = (v11 - rm1[nf]) * INV2W + 0.5f; p = fminf(fmaxf(p, 0.f), 1.f); v11 *= p;

            *reinterpret_cast<float2*>(&Y[(size_t)row * NDIM + col]) =
                make_float2(v00, v01);
            *reinterpret_cast<float2*>(&Y[(size_t)(row + 8) * NDIM + col]) =
                make_float2(v10, v11);
        }
    }
}

// -------------------------------- launcher --------------------------------
extern "C" void kernel_launch(void* const* d_in, const int* in_sizes, int n_in,
                              void* d_out, int out_size)
{
    const float* X      = (const float*)d_in[0];
    const float* W      = (const float*)d_in[1];
    const float* remain = (const float*)d_in[2];
    float* Y            = (float*)d_out;

    split_x_kernel<<<(TOKENS * KDIM / 4 + 255) / 256, 256>>>(X);
    split_w_kernel<<<(NDIM * KDIM / 4 + 255) / 256, 256>>>(W);

    static bool attr_set = false;   // host-side attr set; not graph-captured
    if (!attr_set) {
        cudaFuncSetAttribute(biocell_mma_gemm,
                             cudaFuncAttributeMaxDynamicSharedMemorySize, SMEM_TOTAL);
        attr_set = true;
    }
    dim3 grid(NDIM / BN, TOKENS / BM);   // (16, 256)
    biocell_mma_gemm<<<grid, 256, SMEM_TOTAL>>>(remain, Y);
}